// round 13
// baseline (speedup 1.0000x reference)
#include <cuda_runtime.h>
#include <cuda_fp16.h>

#define N_NODES 100000
#define N_EDGES 1600000
#define D 48

#define T 256
#define ROW_U4 (D / 8)                                   // 6 uint4 per fp16 row
#define AGG_U4 (N_NODES * ROW_U4)                        // 600000 per buffer
#define Z_PAIRS AGG_U4                                   // 2 uint4/thread (one per buffer region pair)
#define N_TILES (N_NODES / 16)                           // 6250 (exact)
#define TILES_PER_GROUP 8
#define NODES_PER_GROUP (TILES_PER_GROUP * 16)           // 128
#define N_GROUPS ((N_TILES + TILES_PER_GROUP - 1) / TILES_PER_GROUP)  // 782
#define MMA_BLOCKS 160                                   // persistent

// Device scratch (no allocations allowed):
__device__ __half g_agg0[N_NODES * D];   // fp16 accumulator, even edges (9.6 MB)
__device__ __half g_agg1[N_NODES * D];   // fp16 accumulator, odd edges  (9.6 MB)

// ---------------------------------------------------------------------------
// Kernel 1: zero both agg buffers. 2 uint4 stores per thread (one per buffer).
// ---------------------------------------------------------------------------
__global__ void zero_kernel() {
    int i = blockIdx.x * blockDim.x + threadIdx.x;
    if (i >= AGG_U4) return;
    uint4 z = make_uint4(0u, 0u, 0u, 0u);
    ((uint4*)g_agg0)[i] = z;
    ((uint4*)g_agg1)[i] = z;
}

// ---------------------------------------------------------------------------
// Kernel 2: COO scatter straight from fp32 x: agg[dst] += a_e * x[src].
// 6 lanes per edge; lane c loads 8 fp32 (32 B, L2-resident), scales, rounds
// to fp16 once, and issues ONE red.v4.f16x2 (16 B) -> contiguous 96 B/edge.
// Edge parity selects the accumulator buffer (shorter fp16 chains).
// ---------------------------------------------------------------------------
__global__ void scatter_kernel(const float* __restrict__ x,
                               const int* __restrict__ src,
                               const int* __restrict__ dst,
                               const float* __restrict__ vals) {
    int tid = blockIdx.x * blockDim.x + threadIdx.x;
    if (tid >= N_EDGES * 6) return;
    int e = tid / 6;
    int c = tid - e * 6;

    int s = __ldg(src + e);
    int d = __ldg(dst + e);
    float a = __ldg(vals + e);

    const float4* xp = (const float4*)(x + (size_t)s * D + c * 8);
    float4 v0 = __ldg(xp);
    float4 v1 = __ldg(xp + 1);

    __half2 h[4];
    h[0] = __floats2half2_rn(a * v0.x, a * v0.y);
    h[1] = __floats2half2_rn(a * v0.z, a * v0.w);
    h[2] = __floats2half2_rn(a * v1.x, a * v1.y);
    h[3] = __floats2half2_rn(a * v1.z, a * v1.w);

    __half* base = (e & 1) ? g_agg1 : g_agg0;
    __half* p = base + (size_t)d * D + c * 8;
    asm volatile("red.global.add.noftz.v4.f16x2 [%0], {%1, %2, %3, %4};"
                 :: "l"(p),
                    "r"(*(const unsigned*)&h[0]), "r"(*(const unsigned*)&h[1]),
                    "r"(*(const unsigned*)&h[2]), "r"(*(const unsigned*)&h[3])
                 : "memory");
}

// ---------------------------------------------------------------------------
// Kernel 3: out = relu((agg0 + agg1) @ w + b) via HMMA m16n8k16.
// Persistent blocks; each iteration stages 128 summed agg rows into smem
// (cooperative uint4 loads, minimal LDG count), then 8 warps pull their
// A-fragments with ldmatrix.x4 and run 18 HMMAs each.
// ---------------------------------------------------------------------------
__global__ void __launch_bounds__(256)
mma_finalize_kernel(const float* __restrict__ w,
                    const float* __restrict__ b,
                    float* __restrict__ out) {
    __shared__ float ws[D * D];
    __shared__ float bs[D];
    __shared__ __half sa[NODES_PER_GROUP * D];     // 12 KB staging (summed agg)

    for (int i = threadIdx.x; i < D * D; i += blockDim.x) ws[i] = w[i];
    if (threadIdx.x < D) bs[threadIdx.x] = b[threadIdx.x];
    __syncthreads();

    int warp = threadIdx.x >> 5;
    int lane = threadIdx.x & 31;
    int gid = lane >> 2;        // group id 0..7 (mma accumulators)
    int tig = lane & 3;         // thread in group 0..3

    // --- B fragments: w (fp32, smem) -> fp16 regs. Built ONCE per warp.
    unsigned bf[3][6][2];
#pragma unroll
    for (int kt = 0; kt < 3; kt++) {
#pragma unroll
        for (int nt = 0; nt < 6; nt++) {
            int n  = nt * 8 + gid;
            int k0 = kt * 16 + tig * 2;
            __half2 h0 = __floats2half2_rn(ws[k0 * D + n], ws[(k0 + 1) * D + n]);
            __half2 h1 = __floats2half2_rn(ws[(k0 + 8) * D + n], ws[(k0 + 9) * D + n]);
            bf[kt][nt][0] = *(const unsigned*)&h0;
            bf[kt][nt][1] = *(const unsigned*)&h1;
        }
    }
    float2 bias[6];
#pragma unroll
    for (int nt = 0; nt < 6; nt++)
        bias[nt] = *(const float2*)(bs + nt * 8 + tig * 2);

    // ldmatrix source address for this lane within its warp's 16-row tile:
    // m = lane>>3 selects quadrant: row += 8 if (m&1); col += 8 if (m>>1).
    int lm_m = lane >> 3;
    int lm_i = lane & 7;
    int lm_row = lm_i + ((lm_m & 1) << 3);       // 0..15 within tile
    int lm_coloff = (lm_m >> 1) << 3;            // 0 or 8

    for (int grp = blockIdx.x; grp < N_GROUPS; grp += MMA_BLOCKS) {
        int node_base = grp * NODES_PER_GROUP;
        int rows = min(NODES_PER_GROUP, N_NODES - node_base);
        int chunks = rows * ROW_U4;              // uint4 chunks to stage

        __syncthreads();                         // protect sa from prev iter readers
        // --- stage: sa = agg0 + agg1 for this group's rows ---
        const uint4* p0 = (const uint4*)(g_agg0 + (size_t)node_base * D);
        const uint4* p1 = (const uint4*)(g_agg1 + (size_t)node_base * D);
        for (int i = threadIdx.x; i < chunks; i += T) {
            uint4 r0 = __ldg(p0 + i);
            uint4 r1 = __ldg(p1 + i);
            const __half2* h0 = (const __half2*)&r0;
            const __half2* h1 = (const __half2*)&r1;
            __half2 s[4];
#pragma unroll
            for (int t = 0; t < 4; t++) s[t] = __hadd2(h0[t], h1[t]);
            ((uint4*)sa)[i] = *(const uint4*)s;
        }
        __syncthreads();

        int tile_in_grp = warp;                  // warp w -> tile w
        int tile = grp * TILES_PER_GROUP + tile_in_grp;
        if (tile < N_TILES) {
            const __half* tile_base = sa + (size_t)tile_in_grp * 16 * D;

            float acc[6][4];
#pragma unroll
            for (int nt = 0; nt < 6; nt++)
#pragma unroll
                for (int t = 0; t < 4; t++) acc[nt][t] = 0.f;

#pragma unroll
            for (int kt = 0; kt < 3; kt++) {
                const __half* src = tile_base + lm_row * D + kt * 16 + lm_coloff;
                unsigned saddr = (unsigned)__cvta_generic_to_shared(src);
                unsigned a0, a1, a2, a3;
                asm volatile(
                    "ldmatrix.sync.aligned.m8n8.x4.shared.b16 {%0,%1,%2,%3}, [%4];"
                    : "=r"(a0), "=r"(a1), "=r"(a2), "=r"(a3) : "r"(saddr));
#pragma unroll
                for (int nt = 0; nt < 6; nt++) {
                    asm volatile(
                        "mma.sync.aligned.m16n8k16.row.col.f32.f16.f16.f32 "
                        "{%0,%1,%2,%3}, {%4,%5,%6,%7}, {%8,%9}, {%0,%1,%2,%3};"
                        : "+f"(acc[nt][0]), "+f"(acc[nt][1]),
                          "+f"(acc[nt][2]), "+f"(acc[nt][3])
                        : "r"(a0), "r"(a1), "r"(a2), "r"(a3),
                          "r"(bf[kt][nt][0]), "r"(bf[kt][nt][1]));
                }
            }

            int nb = tile * 16;
#pragma unroll
            for (int nt = 0; nt < 6; nt++) {
                int col = nt * 8 + tig * 2;
                float2 v0, v1;
                v0.x = fmaxf(acc[nt][0] + bias[nt].x, 0.f);
                v0.y = fmaxf(acc[nt][1] + bias[nt].y, 0.f);
                v1.x = fmaxf(acc[nt][2] + bias[nt].x, 0.f);
                v1.y = fmaxf(acc[nt][3] + bias[nt].y, 0.f);
                *(float2*)(out + (size_t)(nb + gid) * D + col)     = v0;
                *(float2*)(out + (size_t)(nb + gid + 8) * D + col) = v1;
            }
        }
    }
}

// ---------------------------------------------------------------------------
extern "C" void kernel_launch(void* const* d_in, const int* in_sizes, int n_in,
                              void* d_out, int out_size) {
    const float* x        = (const float*)d_in[0];
    const float* w        = (const float*)d_in[1];
    const float* b        = (const float*)d_in[2];
    const int*   edge_src = (const int*)d_in[3];
    const int*   edge_dst = (const int*)d_in[4];
    const float* adj_vals = (const float*)d_in[5];
    float* out = (float*)d_out;

    // 1) zero both agg buffers (2 stores/thread)
    zero_kernel<<<(Z_PAIRS + T - 1) / T, T>>>();
    // 2) scatter straight from fp32 x: agg[dst] += a_e * x[src]
    {
        int total = N_EDGES * 6;
        scatter_kernel<<<(total + T - 1) / T, T>>>(x, edge_src, edge_dst, adj_vals);
    }
    // 3) out = relu((agg0 + agg1) @ w + b): smem-staged A + ldmatrix + HMMA
    mma_finalize_kernel<<<MMA_BLOCKS, T>>>(w, b, out);
}

// round 16
// speedup vs baseline: 1.0041x; 1.0041x over previous
#include <cuda_runtime.h>
#include <cuda_fp16.h>

#define N_NODES 100000
#define N_EDGES 1600000
#define D 48

#define T 256
#define ROW_U4 (D / 8)                                   // 6 uint4 per fp16 row
#define N_TILES (N_NODES / 16)                           // 6250 (exact)
#define MMA_BLOCKS 160                                   // 1280 persistent warps
#define MMA_WARPS (MMA_BLOCKS * (T / 32))
#define SPAD 56   // padded row stride (halves) = 112 B: 16B-aligned rows AND
                  // conflict-free ldmatrix (row r -> banks 28r..28r+3 mod 32, disjoint)

// Device scratch (no allocations allowed):
__device__ __half g_agg0[N_NODES * D];   // fp16 accumulator, even edges (9.6 MB)
__device__ __half g_agg1[N_NODES * D];   // fp16 accumulator, odd edges  (9.6 MB)

// ---------------------------------------------------------------------------
// Kernel 1: COO scatter straight from fp32 x: agg[dst] += a_e * x[src].
// 6 lanes per edge; lane c loads 8 fp32 (32 B, L2-resident), scales, rounds
// to fp16 once, and issues ONE red.v4.f16x2 (16 B) -> contiguous 96 B/edge.
// Edge parity selects the accumulator buffer (shorter fp16 chains).
// ---------------------------------------------------------------------------
__global__ void scatter_kernel(const float* __restrict__ x,
                               const int* __restrict__ src,
                               const int* __restrict__ dst,
                               const float* __restrict__ vals) {
    int tid = blockIdx.x * blockDim.x + threadIdx.x;
    if (tid >= N_EDGES * 6) return;
    int e = tid / 6;
    int c = tid - e * 6;

    int s = __ldg(src + e);
    int d = __ldg(dst + e);
    float a = __ldg(vals + e);

    const float4* xp = (const float4*)(x + (size_t)s * D + c * 8);
    float4 v0 = __ldg(xp);
    float4 v1 = __ldg(xp + 1);

    __half2 h[4];
    h[0] = __floats2half2_rn(a * v0.x, a * v0.y);
    h[1] = __floats2half2_rn(a * v0.z, a * v0.w);
    h[2] = __floats2half2_rn(a * v1.x, a * v1.y);
    h[3] = __floats2half2_rn(a * v1.z, a * v1.w);

    __half* base = (e & 1) ? g_agg1 : g_agg0;
    __half* p = base + (size_t)d * D + c * 8;
    asm volatile("red.global.add.noftz.v4.f16x2 [%0], {%1, %2, %3, %4};"
                 :: "l"(p),
                    "r"(*(const unsigned*)&h[0]), "r"(*(const unsigned*)&h[1]),
                    "r"(*(const unsigned*)&h[2]), "r"(*(const unsigned*)&h[3])
                 : "memory");
}

// ---------------------------------------------------------------------------
// Kernel 2: out = relu((agg0 + agg1) @ w + b) via HMMA m16n8k16.
// Persistent warps. Per tile, the warp stages its 16 summed agg rows into a
// private smem slice with padded stride (112 B -> aligned + conflict-free),
// using 6 coalesced LDG.128 + 3 STS.128 per lane, then 3 ldmatrix.x4 feed
// 18 HMMAs. Only __syncwarp — no block-wide barriers in the loop.
// ---------------------------------------------------------------------------
__global__ void __launch_bounds__(256)
mma_finalize_kernel(const float* __restrict__ w,
                    const float* __restrict__ b,
                    float* __restrict__ out) {
    __shared__ float ws[D * D];
    __shared__ float bs[D];
    __shared__ __half sa[8][16 * SPAD];            // per-warp staging, 14.3 KB

    for (int i = threadIdx.x; i < D * D; i += blockDim.x) ws[i] = w[i];
    if (threadIdx.x < D) bs[threadIdx.x] = b[threadIdx.x];
    __syncthreads();

    int warp = threadIdx.x >> 5;
    int lane = threadIdx.x & 31;
    int gid = lane >> 2;        // group id 0..7
    int tig = lane & 3;         // thread in group 0..3
    int gwarp = blockIdx.x * 8 + warp;

    // --- B fragments: w (fp32, smem) -> fp16 regs. Built ONCE per warp.
    unsigned bf[3][6][2];
#pragma unroll
    for (int kt = 0; kt < 3; kt++) {
#pragma unroll
        for (int nt = 0; nt < 6; nt++) {
            int n  = nt * 8 + gid;
            int k0 = kt * 16 + tig * 2;
            __half2 h0 = __floats2half2_rn(ws[k0 * D + n], ws[(k0 + 1) * D + n]);
            __half2 h1 = __floats2half2_rn(ws[(k0 + 8) * D + n], ws[(k0 + 9) * D + n]);
            bf[kt][nt][0] = *(const unsigned*)&h0;
            bf[kt][nt][1] = *(const unsigned*)&h1;
        }
    }
    float2 bias[6];
#pragma unroll
    for (int nt = 0; nt < 6; nt++)
        bias[nt] = *(const float2*)(bs + nt * 8 + tig * 2);

    __half* slice = sa[warp];

    // ldmatrix source row/col for this lane
    int lm_m = lane >> 3;
    int lm_i = lane & 7;
    int lm_row = lm_i + ((lm_m & 1) << 3);
    int lm_coloff = (lm_m >> 1) << 3;

    for (int tile = gwarp; tile < N_TILES; tile += MMA_WARPS) {
        int node_base = tile * 16;
        const uint4* p0 = (const uint4*)(g_agg0 + (size_t)node_base * D);
        const uint4* p1 = (const uint4*)(g_agg1 + (size_t)node_base * D);

        // --- stage: slice[row][col] = agg0 + agg1 (padded stride) ---
#pragma unroll
        for (int rep = 0; rep < 3; rep++) {
            int i = lane + rep * 32;               // chunk 0..95 (row=i/6, col8=i%6)
            uint4 r0 = __ldg(p0 + i);
            uint4 r1 = __ldg(p1 + i);
            const __half2* h0 = (const __half2*)&r0;
            const __half2* h1 = (const __half2*)&r1;
            __half2 s[4];
#pragma unroll
            for (int t = 0; t < 4; t++) s[t] = __hadd2(h0[t], h1[t]);
            int row = i / 6;
            int col8 = i - row * 6;
            *(uint4*)(slice + row * SPAD + col8 * 8) = *(const uint4*)s;
        }
        __syncwarp();

        float acc[6][4];
#pragma unroll
        for (int nt = 0; nt < 6; nt++)
#pragma unroll
            for (int t = 0; t < 4; t++) acc[nt][t] = 0.f;

#pragma unroll
        for (int kt = 0; kt < 3; kt++) {
            const __half* srcp = slice + lm_row * SPAD + kt * 16 + lm_coloff;
            unsigned saddr = (unsigned)__cvta_generic_to_shared(srcp);
            unsigned a0, a1, a2, a3;
            asm volatile(
                "ldmatrix.sync.aligned.m8n8.x4.shared.b16 {%0,%1,%2,%3}, [%4];"
                : "=r"(a0), "=r"(a1), "=r"(a2), "=r"(a3) : "r"(saddr));
#pragma unroll
            for (int nt = 0; nt < 6; nt++) {
                asm volatile(
                    "mma.sync.aligned.m16n8k16.row.col.f32.f16.f16.f32 "
                    "{%0,%1,%2,%3}, {%4,%5,%6,%7}, {%8,%9}, {%0,%1,%2,%3};"
                    : "+f"(acc[nt][0]), "+f"(acc[nt][1]),
                      "+f"(acc[nt][2]), "+f"(acc[nt][3])
                    : "r"(a0), "r"(a1), "r"(a2), "r"(a3),
                      "r"(bf[kt][nt][0]), "r"(bf[kt][nt][1]));
            }
        }
        __syncwarp();   // next iter's staging must not overwrite live reads

#pragma unroll
        for (int nt = 0; nt < 6; nt++) {
            int col = nt * 8 + tig * 2;
            float2 v0, v1;
            v0.x = fmaxf(acc[nt][0] + bias[nt].x, 0.f);
            v0.y = fmaxf(acc[nt][1] + bias[nt].y, 0.f);
            v1.x = fmaxf(acc[nt][2] + bias[nt].x, 0.f);
            v1.y = fmaxf(acc[nt][3] + bias[nt].y, 0.f);
            *(float2*)(out + (size_t)(node_base + gid) * D + col)     = v0;
            *(float2*)(out + (size_t)(node_base + gid + 8) * D + col) = v1;
        }
    }
}

// ---------------------------------------------------------------------------
extern "C" void kernel_launch(void* const* d_in, const int* in_sizes, int n_in,
                              void* d_out, int out_size) {
    const float* x        = (const float*)d_in[0];
    const float* w        = (const float*)d_in[1];
    const float* b        = (const float*)d_in[2];
    const int*   edge_src = (const int*)d_in[3];
    const int*   edge_dst = (const int*)d_in[4];
    const float* adj_vals = (const float*)d_in[5];
    float* out = (float*)d_out;

    // 1) zero both agg buffers via graph-capturable memset nodes
    void* a0p = nullptr;
    void* a1p = nullptr;
    cudaGetSymbolAddress(&a0p, g_agg0);
    cudaGetSymbolAddress(&a1p, g_agg1);
    cudaMemsetAsync(a0p, 0, (size_t)N_NODES * D * sizeof(__half), 0);
    cudaMemsetAsync(a1p, 0, (size_t)N_NODES * D * sizeof(__half), 0);

    // 2) scatter straight from fp32 x: agg[dst] += a_e * x[src]
    {
        int total = N_EDGES * 6;
        scatter_kernel<<<(total + T - 1) / T, T>>>(x, edge_src, edge_dst, adj_vals);
    }
    // 3) out = relu((agg0 + agg1) @ w + b): warp-private staged A + HMMA
    mma_finalize_kernel<<<MMA_BLOCKS, T>>>(w, b, out);
}